// round 4
// baseline (speedup 1.0000x reference)
#include <cuda_runtime.h>

#define BB 4
#define LL 1024
#define HH 8
#define BL (BB*LL)        // 4096
#define NBH (BB*HH)       // 32

typedef unsigned long long u64;

__device__ __forceinline__ float sqrt_approx(float x){ float y; asm("sqrt.approx.f32 %0, %1;" : "=f"(y) : "f"(x)); return y; }
__device__ __forceinline__ float ex2_approx (float x){ float y; asm("ex2.approx.f32 %0, %1;"  : "=f"(y) : "f"(x)); return y; }
__device__ __forceinline__ u64 pack2(float lo, float hi){ u64 r; asm("mov.b64 %0, {%1,%2};" : "=l"(r) : "f"(lo), "f"(hi)); return r; }
__device__ __forceinline__ float2 unpack2(u64 v){ float2 f; asm("mov.b64 {%0,%1}, %2;" : "=f"(f.x), "=f"(f.y) : "l"(v)); return f; }
__device__ __forceinline__ u64 fma2(u64 a, u64 b, u64 c){ u64 d; asm("fma.rn.f32x2 %0, %1, %2, %3;" : "=l"(d) : "l"(a), "l"(b), "l"(c)); return d; }
__device__ __forceinline__ u64 mul2(u64 a, u64 b){ u64 d; asm("mul.rn.f32x2 %0, %1, %2;" : "=l"(d) : "l"(a), "l"(b)); return d; }
__device__ __forceinline__ u64 add2(u64 a, u64 b){ u64 d; asm("add.rn.f32x2 %0, %1, %2;" : "=l"(d) : "l"(a), "l"(b)); return d; }

// -------- static scratch --------
__device__ float  g_WT  [120*512 + 16];     // W^T: [fused col][dim], +pad for prefetch overrun
__device__ float  g_Rt  [BL*12];            // R (9) + t (3) per (b,l)
__device__ float4 g_QR  [NBH*LL];           // qr_g * wr2
__device__ float4 g_QD  [NBH*LL];           // qd_g * wd2
__device__ float  g_KEYC[NBH*9*LL];         // comp-major keys
__device__ float4 g_PART[NBH*LL*2];         // partial (a0,a1,a2,sum) per key-half

// ============ kernel 0: transpose the 5 projection matrices ============
// grid 20 = 5 matrices x 4 dim-chunks(128); 256 threads
__global__ void __launch_bounds__(256) k_trans(
    const float* __restrict__ W0, const float* __restrict__ W1,
    const float* __restrict__ W2, const float* __restrict__ W3,
    const float* __restrict__ W4)
{
    __shared__ float s[128*25];
    int m = blockIdx.x >> 2;
    int dd0 = (blockIdx.x & 3) * 128;
    const float* W;
    switch (m) {
        case 0: W=W0; break; case 1: W=W1; break; case 2: W=W2; break;
        case 3: W=W3; break; default: W=W4; break;
    }
    int tid = threadIdx.x;
    #pragma unroll
    for (int i=0;i<12;i++) {
        int lin = i*256 + tid;
        if (lin < 3072) {
            int dd = lin / 24, c = lin % 24;
            s[dd*25 + c] = W[dd0*24 + lin];
        }
    }
    __syncthreads();
    #pragma unroll
    for (int i=0;i<12;i++) {
        int lin = i*256 + tid;
        if (lin < 3072) {
            int c = lin >> 7, dd = lin & 127;
            g_WT[(m*24 + c)*512 + dd0 + dd] = s[dd*25 + c];
        }
    }
}

// ============ kernel 1: frames + 5 projections + rotate/scale ============
// 256 threads, 8 rows per block, grid 512
__global__ void __launch_bounds__(256) k_proj(
    const float* __restrict__ x, const float* __restrict__ coords,
    const int* __restrict__ cel,
    const float* __restrict__ b0, const float* __restrict__ b1,
    const float* __restrict__ b2, const float* __restrict__ b3,
    const float* __restrict__ b4,
    const int* __restrict__ mask,
    const float* __restrict__ w_r, const float* __restrict__ w_d)
{
    __shared__ __align__(16) float2 xsp[512][4];   // 16 KB: [dim][row-pair]
    __shared__ __align__(16) float  sres[8*120];
    __shared__ float sRt[8*12];
    __shared__ float sW[2][HH];

    int tid  = threadIdx.x;
    int row0 = blockIdx.x * 8;

    // ---- frames for this block's 8 rows ----
    if (tid < 8) {
        int gl = row0 + tid;
        const float* cp = coords + gl * 9;
        float nx=cp[0], ny=cp[1], nz=cp[2];
        float cax=cp[3], cay=cp[4], caz=cp[5];
        float cx=cp[6], cy=cp[7], cz=cp[8];
        float xx=cax-cx, xy=cay-cy, xz=caz-cz;
        float inv = 1.f / fmaxf(sqrtf(xx*xx + xy*xy + xz*xz), 1e-8f);
        xx*=inv; xy*=inv; xz*=inv;
        float yx=nx-cax, yy=ny-cay, yz=nz-caz;
        float d = xx*yx + xy*yy + xz*yz;
        yx -= d*xx; yy -= d*xy; yz -= d*xz;
        inv = 1.f / fmaxf(sqrtf(yx*yx + yy*yy + yz*yz), 1e-8f);
        yx*=inv; yy*=inv; yz*=inv;
        float zx = xy*yz - xz*yy;
        float zy = xz*yx - xx*yz;
        float zz = xx*yy - xy*yx;
        inv = 1.f / fmaxf(sqrtf(zx*zx + zy*zy + zz*zz), 1e-8f);
        zx*=inv; zy*=inv; zz*=inv;
        float R[12];
        if (cel[gl] != 0) {
            R[0]=xx; R[1]=xy; R[2]=xz; R[3]=yx; R[4]=yy; R[5]=yz;
            R[6]=zx; R[7]=zy; R[8]=zz; R[9]=cax; R[10]=cay; R[11]=caz;
        } else {
            R[0]=1.f;R[1]=0.f;R[2]=0.f; R[3]=0.f;R[4]=1.f;R[5]=0.f;
            R[6]=0.f;R[7]=0.f;R[8]=1.f; R[9]=0.f;R[10]=0.f;R[11]=0.f;
        }
        #pragma unroll
        for (int i=0;i<12;i++) { sRt[tid*12+i] = R[i]; g_Rt[gl*12+i] = R[i]; }
    } else if (tid < 16) {
        int h = tid - 8;
        const float C = 1.44269504088896f * 0.57735026918962f;  // log2e/sqrt3
        sW[0][h] = log1pf(__expf(w_r[h])) * C;
        sW[1][h] = log1pf(__expf(w_d[h])) * C;
    }

    // ---- stage x into row-pair-packed smem ----
    {
        int rp = tid & 3, q = tid >> 2;      // q in [0,64): 8-dim chunk
        const float* rA = x + (size_t)(row0 + 2*rp    )*512 + q*8;
        const float* rB = x + (size_t)(row0 + 2*rp + 1)*512 + q*8;
        #pragma unroll
        for (int i=0;i<8;i+=4) {
            float4 a = *(const float4*)(rA + i);
            float4 b = *(const float4*)(rB + i);
            xsp[q*8+i+0][rp] = make_float2(a.x, b.x);
            xsp[q*8+i+1][rp] = make_float2(a.y, b.y);
            xsp[q*8+i+2][rp] = make_float2(a.z, b.z);
            xsp[q*8+i+3][rp] = make_float2(a.w, b.w);
        }
    }
    __syncthreads();

    // ---- GEMM: 240 threads = 2 row-groups x 120 cols, W^T streamed w/ double buffer ----
    if (tid < 240) {
        int rg = tid / 120;            // row-group: rows 4rg..4rg+3
        int cl = tid % 120;            // fused column
        int m = cl / 24, c = cl % 24;
        const float* bv;
        switch (m) {
            case 0: bv=b0; break; case 1: bv=b1; break; case 2: bv=b2; break;
            case 3: bv=b3; break; default: bv=b4; break;
        }
        float bias = __ldg(bv + c);
        u64 acc0 = pack2(bias, bias);
        u64 acc1 = pack2(bias, bias);

        const float4* w4 = (const float4*)(g_WT + cl*512);
        const ulonglong2* X = (const ulonglong2*)xsp;

        float4 wa0=w4[0], wa1=w4[1], wa2=w4[2], wa3=w4[3];
        #pragma unroll 1
        for (int ch=0; ch<32; ch++) {                 // 32 chunks of 16 dims
            int nb = (ch+1)*4;
            float4 wb0=w4[nb], wb1=w4[nb+1], wb2=w4[nb+2], wb3=w4[nb+3]; // last reads pad
            int base = ch*16;
            #define DO4(WV, OFF)                                             \
            {                                                                \
                int dd = base + OFF;                                         \
                u64 w2;                                                      \
                ulonglong2 xx;                                               \
                w2 = pack2(WV.x, WV.x); xx = X[(dd+0)*2+rg];                 \
                acc0 = fma2(xx.x, w2, acc0); acc1 = fma2(xx.y, w2, acc1);    \
                w2 = pack2(WV.y, WV.y); xx = X[(dd+1)*2+rg];                 \
                acc0 = fma2(xx.x, w2, acc0); acc1 = fma2(xx.y, w2, acc1);    \
                w2 = pack2(WV.z, WV.z); xx = X[(dd+2)*2+rg];                 \
                acc0 = fma2(xx.x, w2, acc0); acc1 = fma2(xx.y, w2, acc1);    \
                w2 = pack2(WV.w, WV.w); xx = X[(dd+3)*2+rg];                 \
                acc0 = fma2(xx.x, w2, acc0); acc1 = fma2(xx.y, w2, acc1);    \
            }
            DO4(wa0, 0) DO4(wa1, 4) DO4(wa2, 8) DO4(wa3, 12)
            #undef DO4
            wa0=wb0; wa1=wb1; wa2=wb2; wa3=wb3;
        }
        float2 v0 = unpack2(acc0), v1 = unpack2(acc1);
        int r0 = rg*4;
        sres[(r0+0)*120 + cl] = v0.x;
        sres[(r0+1)*120 + cl] = v0.y;
        sres[(r0+2)*120 + cl] = v1.x;
        sres[(r0+3)*120 + cl] = v1.y;
    }
    __syncthreads();

    // ---- rotate + scale + store (64 threads = 8 rows x 8 heads) ----
    if (tid < 64) {
        int r = tid >> 3, h = tid & 7;
        int gl = row0 + r;
        float Rm[12];
        #pragma unroll
        for (int i=0;i<12;i++) Rm[i] = sRt[r*12+i];
        const float* rowv = &sres[r*120];
        int base = h*3;

        float qr0=rowv[ 0+base], qr1=rowv[ 1+base], qr2=rowv[ 2+base];
        float kr0=rowv[24+base], kr1=rowv[25+base], kr2=rowv[26+base];
        float qd0=rowv[48+base], qd1=rowv[49+base], qd2=rowv[50+base];
        float kd0=rowv[72+base], kd1=rowv[73+base], kd2=rowv[74+base];
        float vv0=rowv[96+base], vv1=rowv[97+base], vv2=rowv[98+base];

        #define ROT3(o0,o1,o2,a0,a1,a2)                          \
            o0 = a0*Rm[0] + a1*Rm[3] + a2*Rm[6];                 \
            o1 = a0*Rm[1] + a1*Rm[4] + a2*Rm[7];                 \
            o2 = a0*Rm[2] + a1*Rm[5] + a2*Rm[8];
        float qrg0,qrg1,qrg2, krg0,krg1,krg2, qdg0,qdg1,qdg2, kdg0,kdg1,kdg2, vg0,vg1,vg2;
        ROT3(qrg0,qrg1,qrg2, qr0,qr1,qr2);
        ROT3(krg0,krg1,krg2, kr0,kr1,kr2);
        ROT3(qdg0,qdg1,qdg2, qd0,qd1,qd2);
        ROT3(kdg0,kdg1,kdg2, kd0,kd1,kd2);
        ROT3(vg0, vg1, vg2,  vv0,vv1,vv2);
        #undef ROT3

        float wr2 = sW[0][h], wd2 = sW[1][h];
        qdg0 = (qdg0 + Rm[9]) * wd2; qdg1 = (qdg1 + Rm[10]) * wd2; qdg2 = (qdg2 + Rm[11]) * wd2;
        float kn0, kn1, kn2;
        if (mask[gl] == 0) { kn0 = kn1 = kn2 = -1e18f; }
        else {
            kn0 = -(kdg0 + Rm[9] ) * wd2;
            kn1 = -(kdg1 + Rm[10]) * wd2;
            kn2 = -(kdg2 + Rm[11]) * wd2;
        }
        qrg0 *= wr2; qrg1 *= wr2; qrg2 *= wr2;

        int b = gl >> 10, l = gl & 1023;
        int bh = b*HH + h;
        g_QR[bh*LL + l] = make_float4(qrg0, qrg1, qrg2, 0.f);
        g_QD[bh*LL + l] = make_float4(qdg0, qdg1, qdg2, 0.f);
        float* kc = g_KEYC + (size_t)(bh*9)*LL + l;
        kc[0*LL]=krg0; kc[1*LL]=krg1; kc[2*LL]=krg2;
        kc[3*LL]=kn0;  kc[4*LL]=kn1;  kc[5*LL]=kn2;
        kc[6*LL]=vg0;  kc[7*LL]=vg1;  kc[8*LL]=vg2;
    }
}

// ============ kernel 2: attention (key-split partials, f32x2) ============
// grid 512 = bh(32) x qtile(8) x khalf(2); 128 threads; 512 keys in smem
__global__ void __launch_bounds__(128) k_attn()
{
    __shared__ __align__(16) float sK[9*512];   // 18 KB, comp-major
    int tid  = threadIdx.x;
    int kh   = blockIdx.x & 1;
    int tile = (blockIdx.x >> 1) & 7;
    int bh   = blockIdx.x >> 4;

    #pragma unroll
    for (int comp=0; comp<9; comp++)
        ((float4*)sK)[comp*128 + tid] =
            *(const float4*)(g_KEYC + (size_t)(bh*9 + comp)*LL + kh*512 + tid*4);
    __syncthreads();

    int i = tile*128 + tid;
    int q = bh*LL + i;
    float4 QR = g_QR[q];
    float4 QD = g_QD[q];
    u64 qrx = pack2(QR.x, QR.x), qry = pack2(QR.y, QR.y), qrz = pack2(QR.z, QR.z);
    u64 qdx = pack2(QD.x, QD.x), qdy = pack2(QD.y, QD.y), qdz = pack2(QD.z, QD.z);

    const ulonglong2* KRX = (const ulonglong2*)(sK + 0*512);
    const ulonglong2* KRY = (const ulonglong2*)(sK + 1*512);
    const ulonglong2* KRZ = (const ulonglong2*)(sK + 2*512);
    const ulonglong2* KDX = (const ulonglong2*)(sK + 3*512);
    const ulonglong2* KDY = (const ulonglong2*)(sK + 4*512);
    const ulonglong2* KDZ = (const ulonglong2*)(sK + 5*512);
    const ulonglong2* VX  = (const ulonglong2*)(sK + 6*512);
    const ulonglong2* VY  = (const ulonglong2*)(sK + 7*512);
    const ulonglong2* VZ  = (const ulonglong2*)(sK + 8*512);

    u64 sum2 = 0ull, a0 = 0ull, a1 = 0ull, a2 = 0ull;

    #pragma unroll 2
    for (int jj=0; jj<128; jj++) {
        ulonglong2 krx = KRX[jj], kry = KRY[jj], krz = KRZ[jj];
        ulonglong2 kdx = KDX[jj], kdy = KDY[jj], kdz = KDZ[jj];
        ulonglong2 vx  = VX[jj],  vy  = VY[jj],  vz  = VZ[jj];
        {
            u64 dir = fma2(qrz, krz.x, fma2(qry, kry.x, mul2(qrx, krx.x)));
            u64 dx = add2(qdx, kdx.x);
            u64 dy = add2(qdy, kdy.x);
            u64 dz = add2(qdz, kdz.x);
            u64 d2 = fma2(dz, dz, fma2(dy, dy, mul2(dx, dx)));
            float2 d2f = unpack2(d2);
            float2 dirf = unpack2(dir);
            float p0 = ex2_approx(dirf.x - sqrt_approx(d2f.x));
            float p1 = ex2_approx(dirf.y - sqrt_approx(d2f.y));
            u64 p = pack2(p0, p1);
            sum2 = add2(sum2, p);
            a0 = fma2(p, vx.x, a0);
            a1 = fma2(p, vy.x, a1);
            a2 = fma2(p, vz.x, a2);
        }
        {
            u64 dir = fma2(qrz, krz.y, fma2(qry, kry.y, mul2(qrx, krx.y)));
            u64 dx = add2(qdx, kdx.y);
            u64 dy = add2(qdy, kdy.y);
            u64 dz = add2(qdz, kdz.y);
            u64 d2 = fma2(dz, dz, fma2(dy, dy, mul2(dx, dx)));
            float2 d2f = unpack2(d2);
            float2 dirf = unpack2(dir);
            float p0 = ex2_approx(dirf.x - sqrt_approx(d2f.x));
            float p1 = ex2_approx(dirf.y - sqrt_approx(d2f.y));
            u64 p = pack2(p0, p1);
            sum2 = add2(sum2, p);
            a0 = fma2(p, vx.y, a0);
            a1 = fma2(p, vy.y, a1);
            a2 = fma2(p, vz.y, a2);
        }
    }
    float2 s = unpack2(sum2), A0 = unpack2(a0), A1 = unpack2(a1), A2 = unpack2(a2);
    g_PART[q*2 + kh] = make_float4(A0.x+A0.y, A1.x+A1.y, A2.x+A2.y, s.x+s.y);
}

// ============ kernel 3: combine + back-rotate + output projection ============
// 256 threads, 16 rows per block, grid 256
__global__ void __launch_bounds__(256) k_out(
    const float* __restrict__ Wp, const float* __restrict__ bp,
    const int* __restrict__ mask, float* __restrict__ out)
{
    __shared__ __align__(16) float so[16*24];
    __shared__ float smask[16];
    int tid = threadIdx.x;
    int gl0 = blockIdx.x * 16;

    if (tid < 128) {
        int r = tid >> 3, h = tid & 7;
        int gl = gl0 + r;
        int b = gl >> 10, l = gl & 1023;
        int q = (b*HH + h)*LL + l;
        float4 pa = g_PART[q*2 + 0];
        float4 pb = g_PART[q*2 + 1];
        float inv = 1.f / (pa.w + pb.w);
        float o0 = (pa.x + pb.x) * inv;
        float o1 = (pa.y + pb.y) * inv;
        float o2 = (pa.z + pb.z) * inv;
        float Rm[9];
        #pragma unroll
        for (int i=0;i<9;i++) Rm[i] = g_Rt[gl*12 + i];
        so[r*24 + h*3 + 0] = o0*Rm[0] + o1*Rm[3] + o2*Rm[6];
        so[r*24 + h*3 + 1] = o0*Rm[1] + o1*Rm[4] + o2*Rm[7];
        so[r*24 + h*3 + 2] = o0*Rm[2] + o1*Rm[5] + o2*Rm[8];
        if (h == 0) smask[r] = (mask[gl] != 0) ? 1.f : 0.f;
    }
    __syncthreads();

    int c0 = tid, c1 = tid + 256;
    u64 w2a[12], w2b[12];
    #pragma unroll
    for (int fp=0; fp<12; fp++) {
        w2a[fp] = pack2(__ldg(Wp + (2*fp)*512 + c0), __ldg(Wp + (2*fp+1)*512 + c0));
        w2b[fp] = pack2(__ldg(Wp + (2*fp)*512 + c1), __ldg(Wp + (2*fp+1)*512 + c1));
    }
    float ba = __ldg(bp + c0), bbb = __ldg(bp + c1);

    for (int r=0; r<16; r++) {
        const u64* o2 = (const u64*)(so + r*24);
        u64 aa = 0ull, ab = 0ull;
        #pragma unroll
        for (int fp=0; fp<12; fp++) {
            u64 ov = o2[fp];
            aa = fma2(ov, w2a[fp], aa);
            ab = fma2(ov, w2b[fp], ab);
        }
        float2 fa = unpack2(aa), fb = unpack2(ab);
        float mf = smask[r];
        int gl = gl0 + r;
        out[(size_t)gl*512 + c0] = (fa.x + fa.y + ba ) * mf;
        out[(size_t)gl*512 + c1] = (fb.x + fb.y + bbb) * mf;
    }
}

// ================= launch =================
extern "C" void kernel_launch(void* const* d_in, const int* in_sizes, int n_in,
                              void* d_out, int out_size)
{
    const float* x      = (const float*)d_in[0];
    const float* coords = (const float*)d_in[1];
    const int* cel  = (const int*)d_in[2];
    const int* mask = (const int*)d_in[3];
    const float* Wqr = (const float*)d_in[4];  const float* bqr = (const float*)d_in[5];
    const float* Wkr = (const float*)d_in[6];  const float* bkr = (const float*)d_in[7];
    const float* Wqd = (const float*)d_in[8];  const float* bqd = (const float*)d_in[9];
    const float* Wkd = (const float*)d_in[10]; const float* bkd = (const float*)d_in[11];
    const float* Wv  = (const float*)d_in[12]; const float* bv  = (const float*)d_in[13];
    const float* w_r = (const float*)d_in[14]; const float* w_d = (const float*)d_in[15];
    const float* Wp  = (const float*)d_in[16]; const float* bp  = (const float*)d_in[17];

    k_trans<<<20, 256>>>(Wqr, Wkr, Wqd, Wkd, Wv);
    k_proj <<<BL/8, 256>>>(x, coords, cel, bqr, bkr, bqd, bkd, bv, mask, w_r, w_d);
    k_attn <<<NBH*8*2, 128>>>();
    k_out  <<<BL/16, 256>>>(Wp, bp, mask, (float*)d_out);
}

// round 5
// speedup vs baseline: 1.4386x; 1.4386x over previous
#include <cuda_runtime.h>

#define BB 4
#define LL 1024
#define HH 8
#define BL (BB*LL)        // 4096
#define NBH (BB*HH)       // 32

typedef unsigned long long u64;

__device__ __forceinline__ float sqrt_approx(float x){ float y; asm("sqrt.approx.f32 %0, %1;" : "=f"(y) : "f"(x)); return y; }
__device__ __forceinline__ float ex2_approx (float x){ float y; asm("ex2.approx.f32 %0, %1;"  : "=f"(y) : "f"(x)); return y; }
__device__ __forceinline__ u64 pack2(float lo, float hi){ u64 r; asm("mov.b64 %0, {%1,%2};" : "=l"(r) : "f"(lo), "f"(hi)); return r; }
__device__ __forceinline__ float2 unpack2(u64 v){ float2 f; asm("mov.b64 {%0,%1}, %2;" : "=f"(f.x), "=f"(f.y) : "l"(v)); return f; }
__device__ __forceinline__ u64 fma2(u64 a, u64 b, u64 c){ u64 d; asm("fma.rn.f32x2 %0, %1, %2, %3;" : "=l"(d) : "l"(a), "l"(b), "l"(c)); return d; }
__device__ __forceinline__ u64 mul2(u64 a, u64 b){ u64 d; asm("mul.rn.f32x2 %0, %1, %2;" : "=l"(d) : "l"(a), "l"(b)); return d; }
__device__ __forceinline__ u64 add2(u64 a, u64 b){ u64 d; asm("add.rn.f32x2 %0, %1, %2;" : "=l"(d) : "l"(a), "l"(b)); return d; }

// -------- static scratch --------
__device__ float  g_WT  [120*512 + 16];     // W^T: [fused col][dim]
__device__ float  g_Rt  [BL*12];            // R (9) + t (3) per (b,l)
__device__ float4 g_QR  [NBH*LL];           // qr_g * wr2
__device__ float4 g_QD  [NBH*LL];           // qd_g * wd2
__device__ float  g_KEYC[NBH*9*LL];         // comp-major keys
__device__ float4 g_PART[NBH*LL*2];         // partial (a0,a1,a2,sum) per key-half

// ============ kernel 0: transpose the 5 projection matrices ============
// grid 20 = 5 matrices x 4 dim-chunks(128); 256 threads
__global__ void __launch_bounds__(256) k_trans(
    const float* __restrict__ W0, const float* __restrict__ W1,
    const float* __restrict__ W2, const float* __restrict__ W3,
    const float* __restrict__ W4)
{
    __shared__ float s[128*25];
    int m = blockIdx.x >> 2;
    int dd0 = (blockIdx.x & 3) * 128;
    const float* W;
    switch (m) {
        case 0: W=W0; break; case 1: W=W1; break; case 2: W=W2; break;
        case 3: W=W3; break; default: W=W4; break;
    }
    int tid = threadIdx.x;
    #pragma unroll
    for (int i=0;i<12;i++) {
        int lin = i*256 + tid;
        if (lin < 3072) {
            int dd = lin / 24, c = lin % 24;
            s[dd*25 + c] = W[dd0*24 + lin];
        }
    }
    __syncthreads();
    #pragma unroll
    for (int i=0;i<12;i++) {
        int lin = i*256 + tid;
        if (lin < 3072) {
            int c = lin >> 7, dd = lin & 127;
            g_WT[(m*24 + c)*512 + dd0 + dd] = s[dd*25 + c];
        }
    }
}

// ============ kernel 1: frames + 5 projections + rotate/scale ============
// 256 threads, 8 rows per block, grid 512
#define WPITCH 121
__global__ void __launch_bounds__(256) k_proj(
    const float* __restrict__ x, const float* __restrict__ coords,
    const int* __restrict__ cel,
    const float* __restrict__ b0, const float* __restrict__ b1,
    const float* __restrict__ b2, const float* __restrict__ b3,
    const float* __restrict__ b4,
    const int* __restrict__ mask,
    const float* __restrict__ w_r, const float* __restrict__ w_d)
{
    __shared__ __align__(16) float2 xsp[512][4];        // 16 KB: [dim][row-pair]
    __shared__ __align__(16) float  sWt[2][32*WPITCH];  // 31 KB: W tile [d][c], double-buffered
    __shared__ __align__(16) float  sres[8*120];
    __shared__ float sRt[8*12];
    __shared__ float sW[2][HH];

    int tid  = threadIdx.x;
    int row0 = blockIdx.x * 8;

    // ---- frames for this block's 8 rows ----
    if (tid < 8) {
        int gl = row0 + tid;
        const float* cp = coords + gl * 9;
        float nx=cp[0], ny=cp[1], nz=cp[2];
        float cax=cp[3], cay=cp[4], caz=cp[5];
        float cx=cp[6], cy=cp[7], cz=cp[8];
        float xx=cax-cx, xy=cay-cy, xz=caz-cz;
        float inv = 1.f / fmaxf(sqrtf(xx*xx + xy*xy + xz*xz), 1e-8f);
        xx*=inv; xy*=inv; xz*=inv;
        float yx=nx-cax, yy=ny-cay, yz=nz-caz;
        float d = xx*yx + xy*yy + xz*yz;
        yx -= d*xx; yy -= d*xy; yz -= d*xz;
        inv = 1.f / fmaxf(sqrtf(yx*yx + yy*yy + yz*yz), 1e-8f);
        yx*=inv; yy*=inv; yz*=inv;
        float zx = xy*yz - xz*yy;
        float zy = xz*yx - xx*yz;
        float zz = xx*yy - xy*yx;
        inv = 1.f / fmaxf(sqrtf(zx*zx + zy*zy + zz*zz), 1e-8f);
        zx*=inv; zy*=inv; zz*=inv;
        float R[12];
        if (cel[gl] != 0) {
            R[0]=xx; R[1]=xy; R[2]=xz; R[3]=yx; R[4]=yy; R[5]=yz;
            R[6]=zx; R[7]=zy; R[8]=zz; R[9]=cax; R[10]=cay; R[11]=caz;
        } else {
            R[0]=1.f;R[1]=0.f;R[2]=0.f; R[3]=0.f;R[4]=1.f;R[5]=0.f;
            R[6]=0.f;R[7]=0.f;R[8]=1.f; R[9]=0.f;R[10]=0.f;R[11]=0.f;
        }
        #pragma unroll
        for (int i=0;i<12;i++) { sRt[tid*12+i] = R[i]; g_Rt[gl*12+i] = R[i]; }
    } else if (tid < 16) {
        int h = tid - 8;
        const float C = 1.44269504088896f * 0.57735026918962f;  // log2e/sqrt3
        sW[0][h] = log1pf(__expf(w_r[h])) * C;
        sW[1][h] = log1pf(__expf(w_d[h])) * C;
    }

    // ---- stage x into row-pair-packed smem ----
    {
        int rp = tid & 3, q = tid >> 2;      // q in [0,64): 8-dim chunk
        const float* rA = x + (size_t)(row0 + 2*rp    )*512 + q*8;
        const float* rB = x + (size_t)(row0 + 2*rp + 1)*512 + q*8;
        #pragma unroll
        for (int i=0;i<8;i+=4) {
            float4 a = *(const float4*)(rA + i);
            float4 b = *(const float4*)(rB + i);
            xsp[q*8+i+0][rp] = make_float2(a.x, b.x);
            xsp[q*8+i+1][rp] = make_float2(a.y, b.y);
            xsp[q*8+i+2][rp] = make_float2(a.z, b.z);
            xsp[q*8+i+3][rp] = make_float2(a.w, b.w);
        }
    }

    // ---- GEMM: cooperative coalesced W tiles through smem ----
    bool act = tid < 240;
    int cl = tid % 120;            // fused column
    int rg = tid / 120;            // row-group (rows 4rg..4rg+3)
    // W-tile load mapping: float4 idx i in [0,960): c = i>>3, f = i&7
    int wc = tid >> 3;             // this thread's first col   (tid<240 -> wc<30? no: tid 0..239 -> wc 0..29) -- careful
    // Use i = tid + k*240  (k = 0..3)
    const float4* wsrc = (const float4*)g_WT;

    float4 wreg[4];
    // prefetch chunk 0
    if (act) {
        #pragma unroll
        for (int k=0;k<4;k++) {
            int i = tid + k*240;
            int c = i >> 3, f = i & 7;
            wreg[k] = wsrc[c*128 + f];          // chunk 0: dims 0..31
        }
    }
    u64 acc0, acc1;
    {
        int m = cl / 24, c = cl % 24;
        const float* bv;
        switch (m) {
            case 0: bv=b0; break; case 1: bv=b1; break; case 2: bv=b2; break;
            case 3: bv=b3; break; default: bv=b4; break;
        }
        float bias = act ? __ldg(bv + c) : 0.f;
        acc0 = pack2(bias, bias);
        acc1 = pack2(bias, bias);
    }
    // store chunk 0
    if (act) {
        #pragma unroll
        for (int k=0;k<4;k++) {
            int i = tid + k*240;
            int c = i >> 3, f = i & 7;
            #pragma unroll
            for (int j=0;j<4;j++)
                sWt[0][(f*4+j)*WPITCH + c] = ((const float*)&wreg[k])[j];
        }
    }
    __syncthreads();

    const ulonglong2* X = (const ulonglong2*)xsp;
    #pragma unroll 1
    for (int ch=0; ch<16; ch++) {
        int cur = ch & 1;
        // prefetch next chunk into regs (overlaps with compute)
        if (ch < 15 && act) {
            #pragma unroll
            for (int k=0;k<4;k++) {
                int i = tid + k*240;
                int c = i >> 3, f = i & 7;
                wreg[k] = wsrc[c*128 + (ch+1)*8 + f];
            }
        }
        // compute 32 dims from smem
        if (act) {
            const float* wt = &sWt[cur][cl];
            int dbase = ch*64 + rg;
            #pragma unroll
            for (int d=0; d<32; d+=4) {
                float wv0 = wt[(d+0)*WPITCH];
                float wv1 = wt[(d+1)*WPITCH];
                float wv2 = wt[(d+2)*WPITCH];
                float wv3 = wt[(d+3)*WPITCH];
                ulonglong2 x0 = X[dbase + (d+0)*2];
                ulonglong2 x1 = X[dbase + (d+1)*2];
                ulonglong2 x2 = X[dbase + (d+2)*2];
                ulonglong2 x3 = X[dbase + (d+3)*2];
                u64 w2;
                w2 = pack2(wv0, wv0); acc0 = fma2(x0.x, w2, acc0); acc1 = fma2(x0.y, w2, acc1);
                w2 = pack2(wv1, wv1); acc0 = fma2(x1.x, w2, acc0); acc1 = fma2(x1.y, w2, acc1);
                w2 = pack2(wv2, wv2); acc0 = fma2(x2.x, w2, acc0); acc1 = fma2(x2.y, w2, acc1);
                w2 = pack2(wv3, wv3); acc0 = fma2(x3.x, w2, acc0); acc1 = fma2(x3.y, w2, acc1);
            }
        }
        // store next chunk
        if (ch < 15 && act) {
            #pragma unroll
            for (int k=0;k<4;k++) {
                int i = tid + k*240;
                int c = i >> 3, f = i & 7;
                #pragma unroll
                for (int j=0;j<4;j++)
                    sWt[1-cur][(f*4+j)*WPITCH + c] = ((const float*)&wreg[k])[j];
            }
        }
        __syncthreads();
    }

    if (act) {
        float2 v0 = unpack2(acc0), v1 = unpack2(acc1);
        int r0 = rg*4;
        sres[(r0+0)*120 + cl] = v0.x;
        sres[(r0+1)*120 + cl] = v0.y;
        sres[(r0+2)*120 + cl] = v1.x;
        sres[(r0+3)*120 + cl] = v1.y;
    }
    __syncthreads();

    // ---- rotate + scale + store (64 threads = 8 rows x 8 heads) ----
    if (tid < 64) {
        int r = tid >> 3, h = tid & 7;
        int gl = row0 + r;
        float Rm[12];
        #pragma unroll
        for (int i=0;i<12;i++) Rm[i] = sRt[r*12+i];
        const float* rowv = &sres[r*120];
        int base = h*3;

        float qr0=rowv[ 0+base], qr1=rowv[ 1+base], qr2=rowv[ 2+base];
        float kr0=rowv[24+base], kr1=rowv[25+base], kr2=rowv[26+base];
        float qd0=rowv[48+base], qd1=rowv[49+base], qd2=rowv[50+base];
        float kd0=rowv[72+base], kd1=rowv[73+base], kd2=rowv[74+base];
        float vv0=rowv[96+base], vv1=rowv[97+base], vv2=rowv[98+base];

        #define ROT3(o0,o1,o2,a0,a1,a2)                          \
            o0 = a0*Rm[0] + a1*Rm[3] + a2*Rm[6];                 \
            o1 = a0*Rm[1] + a1*Rm[4] + a2*Rm[7];                 \
            o2 = a0*Rm[2] + a1*Rm[5] + a2*Rm[8];
        float qrg0,qrg1,qrg2, krg0,krg1,krg2, qdg0,qdg1,qdg2, kdg0,kdg1,kdg2, vg0,vg1,vg2;
        ROT3(qrg0,qrg1,qrg2, qr0,qr1,qr2);
        ROT3(krg0,krg1,krg2, kr0,kr1,kr2);
        ROT3(qdg0,qdg1,qdg2, qd0,qd1,qd2);
        ROT3(kdg0,kdg1,kdg2, kd0,kd1,kd2);
        ROT3(vg0, vg1, vg2,  vv0,vv1,vv2);
        #undef ROT3

        float wr2 = sW[0][h], wd2 = sW[1][h];
        qdg0 = (qdg0 + Rm[9]) * wd2; qdg1 = (qdg1 + Rm[10]) * wd2; qdg2 = (qdg2 + Rm[11]) * wd2;
        float kn0, kn1, kn2;
        if (mask[gl] == 0) { kn0 = kn1 = kn2 = -1e18f; }
        else {
            kn0 = -(kdg0 + Rm[9] ) * wd2;
            kn1 = -(kdg1 + Rm[10]) * wd2;
            kn2 = -(kdg2 + Rm[11]) * wd2;
        }
        qrg0 *= wr2; qrg1 *= wr2; qrg2 *= wr2;

        int b = gl >> 10, l = gl & 1023;
        int bh = b*HH + h;
        g_QR[bh*LL + l] = make_float4(qrg0, qrg1, qrg2, 0.f);
        g_QD[bh*LL + l] = make_float4(qdg0, qdg1, qdg2, 0.f);
        float* kc = g_KEYC + (size_t)(bh*9)*LL + l;
        kc[0*LL]=krg0; kc[1*LL]=krg1; kc[2*LL]=krg2;
        kc[3*LL]=kn0;  kc[4*LL]=kn1;  kc[5*LL]=kn2;
        kc[6*LL]=vg0;  kc[7*LL]=vg1;  kc[8*LL]=vg2;
    }
}

// ============ kernel 2: attention (key-split partials, f32x2) ============
// grid 512 = bh(32) x qtile(8) x khalf(2); 128 threads; 512 keys in smem
__global__ void __launch_bounds__(128) k_attn()
{
    __shared__ __align__(16) float sK[9*512];   // 18 KB, comp-major
    int tid  = threadIdx.x;
    int kh   = blockIdx.x & 1;
    int tile = (blockIdx.x >> 1) & 7;
    int bh   = blockIdx.x >> 4;

    #pragma unroll
    for (int comp=0; comp<9; comp++)
        ((float4*)sK)[comp*128 + tid] =
            *(const float4*)(g_KEYC + (size_t)(bh*9 + comp)*LL + kh*512 + tid*4);
    __syncthreads();

    int i = tile*128 + tid;
    int q = bh*LL + i;
    float4 QR = g_QR[q];
    float4 QD = g_QD[q];
    u64 qrx = pack2(QR.x, QR.x), qry = pack2(QR.y, QR.y), qrz = pack2(QR.z, QR.z);
    u64 qdx = pack2(QD.x, QD.x), qdy = pack2(QD.y, QD.y), qdz = pack2(QD.z, QD.z);

    const ulonglong2* KRX = (const ulonglong2*)(sK + 0*512);
    const ulonglong2* KRY = (const ulonglong2*)(sK + 1*512);
    const ulonglong2* KRZ = (const ulonglong2*)(sK + 2*512);
    const ulonglong2* KDX = (const ulonglong2*)(sK + 3*512);
    const ulonglong2* KDY = (const ulonglong2*)(sK + 4*512);
    const ulonglong2* KDZ = (const ulonglong2*)(sK + 5*512);
    const ulonglong2* VX  = (const ulonglong2*)(sK + 6*512);
    const ulonglong2* VY  = (const ulonglong2*)(sK + 7*512);
    const ulonglong2* VZ  = (const ulonglong2*)(sK + 8*512);

    u64 sum2 = 0ull, a0 = 0ull, a1 = 0ull, a2 = 0ull;

    #pragma unroll 2
    for (int jj=0; jj<128; jj++) {
        ulonglong2 krx = KRX[jj], kry = KRY[jj], krz = KRZ[jj];
        ulonglong2 kdx = KDX[jj], kdy = KDY[jj], kdz = KDZ[jj];
        ulonglong2 vx  = VX[jj],  vy  = VY[jj],  vz  = VZ[jj];
        {
            u64 dir = fma2(qrz, krz.x, fma2(qry, kry.x, mul2(qrx, krx.x)));
            u64 dx = add2(qdx, kdx.x);
            u64 dy = add2(qdy, kdy.x);
            u64 dz = add2(qdz, kdz.x);
            u64 d2 = fma2(dz, dz, fma2(dy, dy, mul2(dx, dx)));
            float2 d2f = unpack2(d2);
            float2 dirf = unpack2(dir);
            float p0 = ex2_approx(dirf.x - sqrt_approx(d2f.x));
            float p1 = ex2_approx(dirf.y - sqrt_approx(d2f.y));
            u64 p = pack2(p0, p1);
            sum2 = add2(sum2, p);
            a0 = fma2(p, vx.x, a0);
            a1 = fma2(p, vy.x, a1);
            a2 = fma2(p, vz.x, a2);
        }
        {
            u64 dir = fma2(qrz, krz.y, fma2(qry, kry.y, mul2(qrx, krx.y)));
            u64 dx = add2(qdx, kdx.y);
            u64 dy = add2(qdy, kdy.y);
            u64 dz = add2(qdz, kdz.y);
            u64 d2 = fma2(dz, dz, fma2(dy, dy, mul2(dx, dx)));
            float2 d2f = unpack2(d2);
            float2 dirf = unpack2(dir);
            float p0 = ex2_approx(dirf.x - sqrt_approx(d2f.x));
            float p1 = ex2_approx(dirf.y - sqrt_approx(d2f.y));
            u64 p = pack2(p0, p1);
            sum2 = add2(sum2, p);
            a0 = fma2(p, vx.y, a0);
            a1 = fma2(p, vy.y, a1);
            a2 = fma2(p, vz.y, a2);
        }
    }
    float2 s = unpack2(sum2), A0 = unpack2(a0), A1 = unpack2(a1), A2 = unpack2(a2);
    g_PART[q*2 + kh] = make_float4(A0.x+A0.y, A1.x+A1.y, A2.x+A2.y, s.x+s.y);
}

// ============ kernel 3: combine + back-rotate + output projection ============
// 256 threads, 16 rows per block, grid 256
__global__ void __launch_bounds__(256) k_out(
    const float* __restrict__ Wp, const float* __restrict__ bp,
    const int* __restrict__ mask, float* __restrict__ out)
{
    __shared__ __align__(16) float so[16*24];
    __shared__ float smask[16];
    int tid = threadIdx.x;
    int gl0 = blockIdx.x * 16;

    if (tid < 128) {
        int r = tid >> 3, h = tid & 7;
        int gl = gl0 + r;
        int b = gl >> 10, l = gl & 1023;
        int q = (b*HH + h)*LL + l;
        float4 pa = g_PART[q*2 + 0];
        float4 pb = g_PART[q*2 + 1];
        float inv = 1.f / (pa.w + pb.w);
        float o0 = (pa.x + pb.x) * inv;
        float o1 = (pa.y + pb.y) * inv;
        float o2 = (pa.z + pb.z) * inv;
        float Rm[9];
        #pragma unroll
        for (int i=0;i<9;i++) Rm[i] = g_Rt[gl*12 + i];
        so[r*24 + h*3 + 0] = o0*Rm[0] + o1*Rm[3] + o2*Rm[6];
        so[r*24 + h*3 + 1] = o0*Rm[1] + o1*Rm[4] + o2*Rm[7];
        so[r*24 + h*3 + 2] = o0*Rm[2] + o1*Rm[5] + o2*Rm[8];
        if (h == 0) smask[r] = (mask[gl] != 0) ? 1.f : 0.f;
    }
    __syncthreads();

    int c0 = tid, c1 = tid + 256;
    u64 w2a[12], w2b[12];
    #pragma unroll
    for (int fp=0; fp<12; fp++) {
        w2a[fp] = pack2(__ldg(Wp + (2*fp)*512 + c0), __ldg(Wp + (2*fp+1)*512 + c0));
        w2b[fp] = pack2(__ldg(Wp + (2*fp)*512 + c1), __ldg(Wp + (2*fp+1)*512 + c1));
    }
    float ba = __ldg(bp + c0), bbb = __ldg(bp + c1);

    for (int r=0; r<16; r++) {
        const u64* o2 = (const u64*)(so + r*24);
        u64 aa = 0ull, ab = 0ull;
        #pragma unroll
        for (int fp=0; fp<12; fp++) {
            u64 ov = o2[fp];
            aa = fma2(ov, w2a[fp], aa);
            ab = fma2(ov, w2b[fp], ab);
        }
        float2 fa = unpack2(aa), fb = unpack2(ab);
        float mf = smask[r];
        int gl = gl0 + r;
        out[(size_t)gl*512 + c0] = (fa.x + fa.y + ba ) * mf;
        out[(size_t)gl*512 + c1] = (fb.x + fb.y + bbb) * mf;
    }
}

// ================= launch =================
extern "C" void kernel_launch(void* const* d_in, const int* in_sizes, int n_in,
                              void* d_out, int out_size)
{
    const float* x      = (const float*)d_in[0];
    const float* coords = (const float*)d_in[1];
    const int* cel  = (const int*)d_in[2];
    const int* mask = (const int*)d_in[3];
    const float* Wqr = (const float*)d_in[4];  const float* bqr = (const float*)d_in[5];
    const float* Wkr = (const float*)d_in[6];  const float* bkr = (const float*)d_in[7];
    const float* Wqd = (const float*)d_in[8];  const float* bqd = (const float*)d_in[9];
    const float* Wkd = (const float*)d_in[10]; const float* bkd = (const float*)d_in[11];
    const float* Wv  = (const float*)d_in[12]; const float* bv  = (const float*)d_in[13];
    const float* w_r = (const float*)d_in[14]; const float* w_d = (const float*)d_in[15];
    const float* Wp  = (const float*)d_in[16]; const float* bp  = (const float*)d_in[17];

    k_trans<<<20, 256>>>(Wqr, Wkr, Wqd, Wkd, Wv);
    k_proj <<<BL/8, 256>>>(x, coords, cel, bqr, bkr, bqd, bkd, bv, mask, w_r, w_d);
    k_attn <<<NBH*8*2, 128>>>();
    k_out  <<<BL/16, 256>>>(Wp, bp, mask, (float*)d_out);
}